// round 5
// baseline (speedup 1.0000x reference)
#include <cuda_runtime.h>
#include <cuda_bf16.h>
#include <cstdint>

#define LSEQ 8192
#define FIN  1024
#define CDIM 256
#define C3   768
#define NH   8
#define DH   32
#define KS   63

__device__ float g_y[LSEQ * CDIM];
__device__ float g_qkv[LSEQ * C3];
__device__ float g_att[LSEQ * CDIM];

// Pre-split, pre-transposed weights: Wt[n][k] as bf16 hi/lo
__device__ __nv_bfloat16 g_Wp_h[CDIM * FIN],  g_Wp_l[CDIM * FIN];
__device__ __nv_bfloat16 g_Wq_h[C3 * CDIM],   g_Wq_l[C3 * CDIM];
__device__ __nv_bfloat16 g_Wo_h[CDIM * CDIM], g_Wo_l[CDIM * CDIM];

// ---------------------------------------------------------------------------
// Weight prep: W[K][N] -> Wh[n][k], Wl[n][k]  (bf16 hi + bf16 residual)
// ---------------------------------------------------------------------------
__global__ void prep_weights_kernel(const float* __restrict__ W,
                                    __nv_bfloat16* __restrict__ Wh,
                                    __nv_bfloat16* __restrict__ Wl,
                                    int K, int N)
{
    int idx = blockIdx.x * blockDim.x + threadIdx.x;
    if (idx >= K * N) return;
    int k = idx / N;
    int n = idx % N;
    float w = W[idx];
    __nv_bfloat16 h = __float2bfloat16_rn(w);
    __nv_bfloat16 l = __float2bfloat16_rn(w - __bfloat162float(h));
    Wh[(size_t)n * K + k] = h;
    Wl[(size_t)n * K + k] = l;
}

// ---------------------------------------------------------------------------
// bf16 3-split tensor-core GEMM: C[M,N] = A[M,K](fp32) @ W + bias
// W given pre-split/transposed: Wh/Wl[n][k] bf16.
// BM=64 BN=64 BK=16, 128 thr (4 warps 2x2), warp tile 32x32 via m16n8k16.
// D += Ah*Bh + Ah*Bl + Al*Bh.
// ---------------------------------------------------------------------------
#define ASTRIDE 20    // fp32 words per A row (16 + 4 pad)
#define BSTR 24       // bf16 per B row (16 + 8 pad) -> 48B, 16B-aligned chunks

__device__ __forceinline__ void cp16(void* smem, const void* g) {
    uint32_t s = (uint32_t)__cvta_generic_to_shared(smem);
    asm volatile("cp.async.cg.shared.global [%0], [%1], 16;\n" :: "r"(s), "l"(g));
}
__device__ __forceinline__ void cp_commit() {
    asm volatile("cp.async.commit_group;\n");
}

__device__ __forceinline__ void mma_bf16(float* d, const uint32_t* a, uint32_t b0, uint32_t b1) {
    asm volatile(
        "mma.sync.aligned.m16n8k16.row.col.f32.bf16.bf16.f32 "
        "{%0,%1,%2,%3}, {%4,%5,%6,%7}, {%8,%9}, {%0,%1,%2,%3};\n"
        : "+f"(d[0]), "+f"(d[1]), "+f"(d[2]), "+f"(d[3])
        : "r"(a[0]), "r"(a[1]), "r"(a[2]), "r"(a[3]), "r"(b0), "r"(b1));
}

// split two fp32 into packed bf16x2 hi and lo
__device__ __forceinline__ void split2(float x, float y, uint32_t& h, uint32_t& l) {
    __nv_bfloat162 hh = __floats2bfloat162_rn(x, y);
    float2 hf = __bfloat1622float2(hh);
    __nv_bfloat162 ll = __floats2bfloat162_rn(x - hf.x, y - hf.y);
    h = *reinterpret_cast<uint32_t*>(&hh);
    l = *reinterpret_cast<uint32_t*>(&ll);
}

__global__ __launch_bounds__(128) void gemm_bf16s_kernel(
    const float* __restrict__ A,
    const __nv_bfloat16* __restrict__ Wh,
    const __nv_bfloat16* __restrict__ Wl,
    const float* __restrict__ bias, float* __restrict__ C,
    int M, int N, int K)
{
    __shared__ float As[2][64 * ASTRIDE];
    __shared__ __nv_bfloat16 Bsh[2][64 * BSTR];
    __shared__ __nv_bfloat16 Bsl[2][64 * BSTR];

    const int bm = blockIdx.y * 64;
    const int bn = blockIdx.x * 64;
    const int tid = threadIdx.x;
    const int wid = tid >> 5;
    const int lane = tid & 31;
    const int warp_m = wid & 1;     // 0..1
    const int warp_n = wid >> 1;    // 0..1
    const int r = lane >> 2;        // 0..7
    const int c = lane & 3;         // 0..3

    // staging maps
    const int arow = tid >> 1;              // 0..63 (2 chunks/row)
    const int ach  = (tid & 1) * 8;         // fp32 chunk offset 0/8
    const int brow = tid >> 1;              // 0..63
    const int bch  = (tid & 1) * 8;         // bf16 chunk offset 0/8

    float acc[2][4][4];
    #pragma unroll
    for (int i = 0; i < 2; i++)
        #pragma unroll
        for (int j = 0; j < 4; j++)
            #pragma unroll
            for (int e = 0; e < 4; e++) acc[i][j][e] = 0.f;

    const int T = K >> 4;

    // prologue: tile 0 -> buf 0
    {
        cp16(&As[0][arow * ASTRIDE + ach],     &A[(size_t)(bm + arow) * K + ach]);
        cp16(&As[0][arow * ASTRIDE + ach + 4], &A[(size_t)(bm + arow) * K + ach + 4]);
        cp16(&Bsh[0][brow * BSTR + bch], &Wh[(size_t)(bn + brow) * K + bch]);
        cp16(&Bsl[0][brow * BSTR + bch], &Wl[(size_t)(bn + brow) * K + bch]);
        cp_commit();
    }

    for (int kt = 0; kt < T; kt++) {
        const int buf = kt & 1;
        if (kt + 1 < T) {
            const int k0 = (kt + 1) << 4;
            const int nb = buf ^ 1;
            cp16(&As[nb][arow * ASTRIDE + ach],     &A[(size_t)(bm + arow) * K + k0 + ach]);
            cp16(&As[nb][arow * ASTRIDE + ach + 4], &A[(size_t)(bm + arow) * K + k0 + ach + 4]);
            cp16(&Bsh[nb][brow * BSTR + bch], &Wh[(size_t)(bn + brow) * K + k0 + bch]);
            cp16(&Bsl[nb][brow * BSTR + bch], &Wl[(size_t)(bn + brow) * K + k0 + bch]);
            cp_commit();
            asm volatile("cp.async.wait_group 1;\n");
        } else {
            asm volatile("cp.async.wait_group 0;\n");
        }
        __syncthreads();

        const float* as = As[buf];
        const __nv_bfloat16* bsh = Bsh[buf];
        const __nv_bfloat16* bsl = Bsl[buf];

        // A fragments (fp32 -> bf16 hi/lo), one k16 step
        uint32_t ah[2][4], al[2][4];
        #pragma unroll
        for (int mi = 0; mi < 2; mi++) {
            int m0 = warp_m * 32 + mi * 16;
            float2 f0 = *(const float2*)&as[(m0 + r)     * ASTRIDE + 2 * c];
            float2 f1 = *(const float2*)&as[(m0 + r + 8) * ASTRIDE + 2 * c];
            float2 f2 = *(const float2*)&as[(m0 + r)     * ASTRIDE + 2 * c + 8];
            float2 f3 = *(const float2*)&as[(m0 + r + 8) * ASTRIDE + 2 * c + 8];
            split2(f0.x, f0.y, ah[mi][0], al[mi][0]);
            split2(f1.x, f1.y, ah[mi][1], al[mi][1]);
            split2(f2.x, f2.y, ah[mi][2], al[mi][2]);
            split2(f3.x, f3.y, ah[mi][3], al[mi][3]);
        }

        #pragma unroll
        for (int nj = 0; nj < 4; nj++) {
            int n = warp_n * 32 + nj * 8 + r;
            uint32_t b0h = *(const uint32_t*)&bsh[n * BSTR + 2 * c];
            uint32_t b1h = *(const uint32_t*)&bsh[n * BSTR + 2 * c + 8];
            uint32_t b0l = *(const uint32_t*)&bsl[n * BSTR + 2 * c];
            uint32_t b1l = *(const uint32_t*)&bsl[n * BSTR + 2 * c + 8];
            #pragma unroll
            for (int mi = 0; mi < 2; mi++) {
                mma_bf16(acc[mi][nj], al[mi], b0h, b1h);
                mma_bf16(acc[mi][nj], ah[mi], b0l, b1l);
                mma_bf16(acc[mi][nj], ah[mi], b0h, b1h);
            }
        }
        __syncthreads();
    }

    // epilogue
    #pragma unroll
    for (int mi = 0; mi < 2; mi++) {
        #pragma unroll
        for (int nj = 0; nj < 4; nj++) {
            int row = bm + warp_m * 32 + mi * 16 + r;
            int col = bn + warp_n * 32 + nj * 8 + c * 2;
            float2 bb = *(const float2*)&bias[col];
            float2 o0, o1;
            o0.x = acc[mi][nj][0] + bb.x;
            o0.y = acc[mi][nj][1] + bb.y;
            o1.x = acc[mi][nj][2] + bb.x;
            o1.y = acc[mi][nj][3] + bb.y;
            *(float2*)&C[(size_t)row * N + col] = o0;
            *(float2*)&C[(size_t)(row + 8) * N + col] = o1;
        }
    }
}

// ---------------------------------------------------------------------------
// NATTEN-1D (unchanged from round 4)
// ---------------------------------------------------------------------------
#define TQ 64
#define KV 126
#define RS 36
#define PTS 12
#define PTROWS 72

__device__ __forceinline__ int win_start(int l) {
    int s = l - 31;
    if (s < 0) s = 0;
    if (s > LSEQ - KS) s = LSEQ - KS;
    return s;
}

__global__ __launch_bounds__(256) void natten_kernel(
    const float* __restrict__ qkv, float* __restrict__ out)
{
    extern __shared__ float sm[];
    float* Ks = sm;
    float* Vs = Ks + 127 * RS;
    float* Qs = Vs + 127 * RS;
    float* Pt = Qs + TQ * RS;

    const int t0 = blockIdx.x * TQ;
    const int h = blockIdx.y;
    const int tid = threadIdx.x;
    const int w = tid >> 5;
    const int lane = tid & 31;

    int base = t0 - 31;
    if (base < 0) base = 0;
    if (base > LSEQ - KV) base = LSEQ - KV;

    const float scale = 0.17677669529663687f;

    for (int idx = tid; idx < KV * 32; idx += 256) {
        int row = idx >> 5;
        int d = idx & 31;
        size_t g = (size_t)(base + row) * C3 + CDIM + h * DH + d;
        Ks[row * RS + d] = qkv[g];
        Vs[row * RS + d] = qkv[g + CDIM];
    }
    if (tid < 32) {
        Ks[126 * RS + tid] = 0.f;
        Vs[126 * RS + tid] = 0.f;
    }
    for (int idx = tid; idx < TQ * 32; idx += 256) {
        int row = idx >> 5;
        int d = idx & 31;
        Qs[row * RS + d] = qkv[(size_t)(t0 + row) * C3 + h * DH + d] * scale;
    }
    for (int idx = tid; idx < 8 * PTROWS * PTS; idx += 256)
        Pt[idx] = 0.f;
    __syncthreads();

    const int l0 = t0 + w * 8;
    const int ws0 = win_start(l0) - base;
    const int ws7 = win_start(l0 + 7) - base;
    float* Ptw = Pt + w * PTROWS * PTS;

    #pragma unroll 1
    for (int qi = 0; qi < 8; qi++) {
        const int lq = w * 8 + qi;
        const int l = t0 + lq;
        const int ws = win_start(l) - base;

        const float4* k0p = (const float4*)&Ks[(ws + lane) * RS];
        const float4* k1p = (const float4*)&Ks[(ws + 32 + lane) * RS];
        const float4* qp  = (const float4*)&Qs[lq * RS];

        float s0 = 0.f, s1 = 0.f;
        #pragma unroll
        for (int d4 = 0; d4 < 8; d4++) {
            float4 q4 = qp[d4];
            float4 ka = k0p[d4];
            float4 kb = k1p[d4];
            s0 += q4.x * ka.x + q4.y * ka.y + q4.z * ka.z + q4.w * ka.w;
            s1 += q4.x * kb.x + q4.y * kb.y + q4.z * kb.z + q4.w * kb.w;
        }

        float m = fmaxf(s0, (lane < 31) ? s1 : -1e30f);
        #pragma unroll
        for (int o = 16; o > 0; o >>= 1)
            m = fmaxf(m, __shfl_xor_sync(0xffffffffu, m, o));
        float e0 = __expf(s0 - m);
        float e1 = (lane < 31) ? __expf(s1 - m) : 0.f;
        float sum = e0 + e1;
        #pragma unroll
        for (int o = 16; o > 0; o >>= 1)
            sum += __shfl_xor_sync(0xffffffffu, sum, o);
        float inv = __frcp_rn(sum);

        const int off = ws - ws0;
        Ptw[(off + lane) * PTS + qi]      = e0 * inv;
        Ptw[(off + 32 + lane) * PTS + qi] = e1 * inv;
    }
    __syncwarp();

    const int nU = ws7 - ws0 + 64;
    float acc[8];
    #pragma unroll
    for (int q = 0; q < 8; q++) acc[q] = 0.f;

    const float* vb = &Vs[ws0 * RS + lane];
    #pragma unroll 4
    for (int jj = 0; jj < nU; jj++) {
        float v = vb[jj * RS];
        float4 pa = *(const float4*)&Ptw[jj * PTS];
        float4 pb = *(const float4*)&Ptw[jj * PTS + 4];
        acc[0] = fmaf(pa.x, v, acc[0]);
        acc[1] = fmaf(pa.y, v, acc[1]);
        acc[2] = fmaf(pa.z, v, acc[2]);
        acc[3] = fmaf(pa.w, v, acc[3]);
        acc[4] = fmaf(pb.x, v, acc[4]);
        acc[5] = fmaf(pb.y, v, acc[5]);
        acc[6] = fmaf(pb.z, v, acc[6]);
        acc[7] = fmaf(pb.w, v, acc[7]);
    }

    #pragma unroll
    for (int q = 0; q < 8; q++)
        out[(size_t)(l0 + q) * CDIM + h * DH + lane] = acc[q];
}

// ---------------------------------------------------------------------------
extern "C" void kernel_launch(void* const* d_in, const int* in_sizes, int n_in,
                              void* d_out, int out_size)
{
    const float* x    = (const float*)d_in[0];
    const float* Wp   = (const float*)d_in[1];
    const float* bp   = (const float*)d_in[2];
    const float* Wqkv = (const float*)d_in[3];
    const float* bqkv = (const float*)d_in[4];
    const float* Wo   = (const float*)d_in[5];
    const float* bo   = (const float*)d_in[6];
    float* out = (float*)d_out;

    float *p_y, *p_qkv, *p_att;
    cudaGetSymbolAddress((void**)&p_y,   g_y);
    cudaGetSymbolAddress((void**)&p_qkv, g_qkv);
    cudaGetSymbolAddress((void**)&p_att, g_att);

    __nv_bfloat16 *wph, *wpl, *wqh, *wql, *woh, *wol;
    cudaGetSymbolAddress((void**)&wph, g_Wp_h);
    cudaGetSymbolAddress((void**)&wpl, g_Wp_l);
    cudaGetSymbolAddress((void**)&wqh, g_Wq_h);
    cudaGetSymbolAddress((void**)&wql, g_Wq_l);
    cudaGetSymbolAddress((void**)&woh, g_Wo_h);
    cudaGetSymbolAddress((void**)&wol, g_Wo_l);

    const int natten_smem = (127 * RS * 2 + TQ * RS + 8 * PTROWS * PTS) * 4;
    static bool attr_set = false;
    if (!attr_set) {
        cudaFuncSetAttribute(natten_kernel,
                             cudaFuncAttributeMaxDynamicSharedMemorySize,
                             natten_smem);
        attr_set = true;
    }

    // weight prep (tiny)
    prep_weights_kernel<<<(FIN * CDIM + 255) / 256, 256>>>(Wp, wph, wpl, FIN, CDIM);
    prep_weights_kernel<<<(CDIM * C3 + 255) / 256, 256>>>(Wqkv, wqh, wql, CDIM, C3);
    prep_weights_kernel<<<(CDIM * CDIM + 255) / 256, 256>>>(Wo, woh, wol, CDIM, CDIM);

    // y = x @ Wp + bp
    gemm_bf16s_kernel<<<dim3(CDIM / 64, LSEQ / 64), 128>>>(
        x, wph, wpl, bp, p_y, LSEQ, CDIM, FIN);

    // qkv = y @ Wqkv + bqkv
    gemm_bf16s_kernel<<<dim3(C3 / 64, LSEQ / 64), 128>>>(
        p_y, wqh, wql, bqkv, p_qkv, LSEQ, C3, CDIM);

    natten_kernel<<<dim3(LSEQ / TQ, NH), 256, natten_smem>>>(p_qkv, p_att);

    // out = att @ Wo + bo
    gemm_bf16s_kernel<<<dim3(CDIM / 64, LSEQ / 64), 128>>>(
        p_att, woh, wol, bo, out, LSEQ, CDIM, CDIM);
}

// round 8
// speedup vs baseline: 1.4525x; 1.4525x over previous
#include <cuda_runtime.h>
#include <cuda_bf16.h>
#include <cstdint>

#define LSEQ 8192
#define FIN  1024
#define CDIM 256
#define C3   768
#define NH   8
#define DH   32
#define KS   63

__device__ float g_y[LSEQ * CDIM];
__device__ float g_qkv[LSEQ * C3];
__device__ float g_att[LSEQ * CDIM];

// Pre-rounded (tf32 RNE) weights, original [K][N] layout
__device__ float g_Wp_r[FIN * CDIM];
__device__ float g_Wq_r[CDIM * C3];
__device__ float g_Wo_r[CDIM * CDIM];

// ---------------------------------------------------------------------------
// helpers
// ---------------------------------------------------------------------------
__device__ __forceinline__ void cp16(void* smem, const void* g) {
    uint32_t s = (uint32_t)__cvta_generic_to_shared(smem);
    asm volatile("cp.async.cg.shared.global [%0], [%1], 16;\n" :: "r"(s), "l"(g));
}
__device__ __forceinline__ void cp_commit() {
    asm volatile("cp.async.commit_group;\n");
}
__device__ __forceinline__ void mma_tf32(float* d, const uint32_t* a, const uint32_t* b) {
    asm volatile(
        "mma.sync.aligned.m16n8k8.row.col.f32.tf32.tf32.f32 "
        "{%0,%1,%2,%3}, {%4,%5,%6,%7}, {%8,%9}, {%0,%1,%2,%3};\n"
        : "+f"(d[0]), "+f"(d[1]), "+f"(d[2]), "+f"(d[3])
        : "r"(a[0]), "r"(a[1]), "r"(a[2]), "r"(a[3]), "r"(b[0]), "r"(b[1]));
}
__device__ __forceinline__ uint32_t cvt_rna_tf32(float x) {
    uint32_t r;
    asm("cvt.rna.tf32.f32 %0, %1;" : "=r"(r) : "f"(x));
    return r;
}

// ---------------------------------------------------------------------------
// Weight prep: round W to tf32 (RNE), same [K][N] layout
// ---------------------------------------------------------------------------
__global__ void prep_weights_kernel(const float* __restrict__ W,
                                    float* __restrict__ Wr, int total)
{
    int idx = blockIdx.x * blockDim.x + threadIdx.x;
    if (idx >= total) return;
    uint32_t t = cvt_rna_tf32(W[idx]);
    Wr[idx] = __uint_as_float(t);
}

// ---------------------------------------------------------------------------
// Single-pass TF32 GEMM (RNE operands): C[M,N] = A[M,K] @ B[K,N] + bias
// BM=128 BN=64 BK=16, 256 thr (8 warps, 4x2), warp tile 32x32 via m16n8k8.
// B pre-rounded in gmem; A rounded inline via cvt.rna after LDS.
// ---------------------------------------------------------------------------
#define ASTRIDE 20
#define BSTRIDE 72

__global__ __launch_bounds__(256) void gemm_tf32_kernel(
    const float* __restrict__ A, const float* __restrict__ B,
    const float* __restrict__ bias, float* __restrict__ C,
    int M, int N, int K)
{
    __shared__ float As[2][128 * ASTRIDE];
    __shared__ float Bs[2][16 * BSTRIDE];

    const int bm = blockIdx.y * 128;
    const int bn = blockIdx.x * 64;
    const int tid = threadIdx.x;
    const int wid = tid >> 5;
    const int lane = tid & 31;
    const int warp_m = wid & 3;
    const int warp_n = wid >> 2;
    const int r = lane >> 2;
    const int c = lane & 3;

    const int arow0 = tid >> 2;
    const int ac4   = (tid & 3) * 4;
    const int brow  = tid >> 4;
    const int bc4   = (tid & 15) * 4;

    float acc[2][4][4];
    #pragma unroll
    for (int i = 0; i < 2; i++)
        #pragma unroll
        for (int j = 0; j < 4; j++)
            #pragma unroll
            for (int e = 0; e < 4; e++) acc[i][j][e] = 0.f;

    const int T = K >> 4;

    {
        cp16(&As[0][arow0 * ASTRIDE + ac4], &A[(size_t)(bm + arow0) * K + ac4]);
        cp16(&As[0][(arow0 + 64) * ASTRIDE + ac4], &A[(size_t)(bm + arow0 + 64) * K + ac4]);
        cp16(&Bs[0][brow * BSTRIDE + bc4], &B[(size_t)brow * N + bn + bc4]);
        cp_commit();
    }

    for (int kt = 0; kt < T; kt++) {
        const int buf = kt & 1;
        if (kt + 1 < T) {
            const int k0 = (kt + 1) << 4;
            const int nb = buf ^ 1;
            cp16(&As[nb][arow0 * ASTRIDE + ac4], &A[(size_t)(bm + arow0) * K + k0 + ac4]);
            cp16(&As[nb][(arow0 + 64) * ASTRIDE + ac4], &A[(size_t)(bm + arow0 + 64) * K + k0 + ac4]);
            cp16(&Bs[nb][brow * BSTRIDE + bc4], &B[(size_t)(k0 + brow) * N + bn + bc4]);
            cp_commit();
            asm volatile("cp.async.wait_group 1;\n");
        } else {
            asm volatile("cp.async.wait_group 0;\n");
        }
        __syncthreads();

        const float* as = As[buf];
        const float* bs = Bs[buf];
        #pragma unroll
        for (int ks = 0; ks < 16; ks += 8) {
            uint32_t af[2][4], bf[4][2];
            #pragma unroll
            for (int mi = 0; mi < 2; mi++) {
                int m0 = warp_m * 32 + mi * 16;
                af[mi][0] = cvt_rna_tf32(as[(m0 + r)     * ASTRIDE + ks + c]);
                af[mi][1] = cvt_rna_tf32(as[(m0 + r + 8) * ASTRIDE + ks + c]);
                af[mi][2] = cvt_rna_tf32(as[(m0 + r)     * ASTRIDE + ks + c + 4]);
                af[mi][3] = cvt_rna_tf32(as[(m0 + r + 8) * ASTRIDE + ks + c + 4]);
            }
            #pragma unroll
            for (int nj = 0; nj < 4; nj++) {
                int n0 = warp_n * 32 + nj * 8 + r;
                bf[nj][0] = __float_as_uint(bs[(ks + c)     * BSTRIDE + n0]);
                bf[nj][1] = __float_as_uint(bs[(ks + c + 4) * BSTRIDE + n0]);
            }
            #pragma unroll
            for (int mi = 0; mi < 2; mi++)
                #pragma unroll
                for (int nj = 0; nj < 4; nj++)
                    mma_tf32(acc[mi][nj], af[mi], bf[nj]);
        }
        __syncthreads();
    }

    #pragma unroll
    for (int mi = 0; mi < 2; mi++) {
        #pragma unroll
        for (int nj = 0; nj < 4; nj++) {
            int row = bm + warp_m * 32 + mi * 16 + r;
            int col = bn + warp_n * 32 + nj * 8 + c * 2;
            float2 bb = *(const float2*)&bias[col];
            float2 o0, o1;
            o0.x = acc[mi][nj][0] + bb.x;
            o0.y = acc[mi][nj][1] + bb.y;
            o1.x = acc[mi][nj][2] + bb.x;
            o1.y = acc[mi][nj][3] + bb.y;
            *(float2*)&C[(size_t)row * N + col] = o0;
            *(float2*)&C[(size_t)(row + 8) * N + col] = o1;
        }
    }
}

// ---------------------------------------------------------------------------
// NATTEN-1D (unchanged from round 4)
// ---------------------------------------------------------------------------
#define TQ 64
#define KV 126
#define RS 36
#define PTS 12
#define PTROWS 72

__device__ __forceinline__ int win_start(int l) {
    int s = l - 31;
    if (s < 0) s = 0;
    if (s > LSEQ - KS) s = LSEQ - KS;
    return s;
}

__global__ __launch_bounds__(256) void natten_kernel(
    const float* __restrict__ qkv, float* __restrict__ out)
{
    extern __shared__ float sm[];
    float* Ks = sm;
    float* Vs = Ks + 127 * RS;
    float* Qs = Vs + 127 * RS;
    float* Pt = Qs + TQ * RS;

    const int t0 = blockIdx.x * TQ;
    const int h = blockIdx.y;
    const int tid = threadIdx.x;
    const int w = tid >> 5;
    const int lane = tid & 31;

    int base = t0 - 31;
    if (base < 0) base = 0;
    if (base > LSEQ - KV) base = LSEQ - KV;

    const float scale = 0.17677669529663687f;

    for (int idx = tid; idx < KV * 32; idx += 256) {
        int row = idx >> 5;
        int d = idx & 31;
        size_t g = (size_t)(base + row) * C3 + CDIM + h * DH + d;
        Ks[row * RS + d] = qkv[g];
        Vs[row * RS + d] = qkv[g + CDIM];
    }
    if (tid < 32) {
        Ks[126 * RS + tid] = 0.f;
        Vs[126 * RS + tid] = 0.f;
    }
    for (int idx = tid; idx < TQ * 32; idx += 256) {
        int row = idx >> 5;
        int d = idx & 31;
        Qs[row * RS + d] = qkv[(size_t)(t0 + row) * C3 + h * DH + d] * scale;
    }
    for (int idx = tid; idx < 8 * PTROWS * PTS; idx += 256)
        Pt[idx] = 0.f;
    __syncthreads();

    const int l0 = t0 + w * 8;
    const int ws0 = win_start(l0) - base;
    const int ws7 = win_start(l0 + 7) - base;
    float* Ptw = Pt + w * PTROWS * PTS;

    #pragma unroll 1
    for (int qi = 0; qi < 8; qi++) {
        const int lq = w * 8 + qi;
        const int l = t0 + lq;
        const int ws = win_start(l) - base;

        const float4* k0p = (const float4*)&Ks[(ws + lane) * RS];
        const float4* k1p = (const float4*)&Ks[(ws + 32 + lane) * RS];
        const float4* qp  = (const float4*)&Qs[lq * RS];

        float s0 = 0.f, s1 = 0.f;
        #pragma unroll
        for (int d4 = 0; d4 < 8; d4++) {
            float4 q4 = qp[d4];
            float4 ka = k0p[d4];
            float4 kb = k1p[d4];
            s0 += q4.x * ka.x + q4.y * ka.y + q4.z * ka.z + q4.w * ka.w;
            s1 += q4.x * kb.x + q4.y * kb.y + q4.z * kb.z + q4.w * kb.w;
        }

        float m = fmaxf(s0, (lane < 31) ? s1 : -1e30f);
        #pragma unroll
        for (int o = 16; o > 0; o >>= 1)
            m = fmaxf(m, __shfl_xor_sync(0xffffffffu, m, o));
        float e0 = __expf(s0 - m);
        float e1 = (lane < 31) ? __expf(s1 - m) : 0.f;
        float sum = e0 + e1;
        #pragma unroll
        for (int o = 16; o > 0; o >>= 1)
            sum += __shfl_xor_sync(0xffffffffu, sum, o);
        float inv = __frcp_rn(sum);

        const int off = ws - ws0;
        Ptw[(off + lane) * PTS + qi]      = e0 * inv;
        Ptw[(off + 32 + lane) * PTS + qi] = e1 * inv;
    }
    __syncwarp();

    const int nU = ws7 - ws0 + 64;
    float acc[8];
    #pragma unroll
    for (int q = 0; q < 8; q++) acc[q] = 0.f;

    const float* vb = &Vs[ws0 * RS + lane];
    #pragma unroll 4
    for (int jj = 0; jj < nU; jj++) {
        float v = vb[jj * RS];
        float4 pa = *(const float4*)&Ptw[jj * PTS];
        float4 pb = *(const float4*)&Ptw[jj * PTS + 4];
        acc[0] = fmaf(pa.x, v, acc[0]);
        acc[1] = fmaf(pa.y, v, acc[1]);
        acc[2] = fmaf(pa.z, v, acc[2]);
        acc[3] = fmaf(pa.w, v, acc[3]);
        acc[4] = fmaf(pb.x, v, acc[4]);
        acc[5] = fmaf(pb.y, v, acc[5]);
        acc[6] = fmaf(pb.z, v, acc[6]);
        acc[7] = fmaf(pb.w, v, acc[7]);
    }

    #pragma unroll
    for (int q = 0; q < 8; q++)
        out[(size_t)(l0 + q) * CDIM + h * DH + lane] = acc[q];
}

// ---------------------------------------------------------------------------
extern "C" void kernel_launch(void* const* d_in, const int* in_sizes, int n_in,
                              void* d_out, int out_size)
{
    const float* x    = (const float*)d_in[0];
    const float* Wp   = (const float*)d_in[1];
    const float* bp   = (const float*)d_in[2];
    const float* Wqkv = (const float*)d_in[3];
    const float* bqkv = (const float*)d_in[4];
    const float* Wo   = (const float*)d_in[5];
    const float* bo   = (const float*)d_in[6];
    float* out = (float*)d_out;

    float *p_y, *p_qkv, *p_att, *wpr, *wqr, *wor;
    cudaGetSymbolAddress((void**)&p_y,   g_y);
    cudaGetSymbolAddress((void**)&p_qkv, g_qkv);
    cudaGetSymbolAddress((void**)&p_att, g_att);
    cudaGetSymbolAddress((void**)&wpr, g_Wp_r);
    cudaGetSymbolAddress((void**)&wqr, g_Wq_r);
    cudaGetSymbolAddress((void**)&wor, g_Wo_r);

    const int natten_smem = (127 * RS * 2 + TQ * RS + 8 * PTROWS * PTS) * 4;
    static bool attr_set = false;
    if (!attr_set) {
        cudaFuncSetAttribute(natten_kernel,
                             cudaFuncAttributeMaxDynamicSharedMemorySize,
                             natten_smem);
        attr_set = true;
    }

    // round weights to tf32 RNE (tiny elementwise kernels)
    prep_weights_kernel<<<(FIN * CDIM + 255) / 256, 256>>>(Wp, wpr, FIN * CDIM);
    prep_weights_kernel<<<(CDIM * C3 + 255) / 256, 256>>>(Wqkv, wqr, CDIM * C3);
    prep_weights_kernel<<<(CDIM * CDIM + 255) / 256, 256>>>(Wo, wor, CDIM * CDIM);

    // y = x @ Wp + bp
    gemm_tf32_kernel<<<dim3(CDIM / 64, LSEQ / 128), 256>>>(
        x, wpr, bp, p_y, LSEQ, CDIM, FIN);

    // qkv = y @ Wqkv + bqkv
    gemm_tf32_kernel<<<dim3(C3 / 64, LSEQ / 128), 256>>>(
        p_y, wqr, bqkv, p_qkv, LSEQ, C3, CDIM);

    natten_kernel<<<dim3(LSEQ / TQ, NH), 256, natten_smem>>>(p_qkv, p_att);

    // out = att @ Wo + bo
    gemm_tf32_kernel<<<dim3(CDIM / 64, LSEQ / 128), 256>>>(
        p_att, wor, bo, out, LSEQ, CDIM, CDIM);
}